// round 9
// baseline (speedup 1.0000x reference)
#include <cuda_runtime.h>
#include <cuda_fp16.h>
#include <cstdint>

#define NE 16
#define DIN 128
#define HID 512
#define DOUT 64
#define BATCH 8192

// ---------------- device scratch ----------------
// weights: [e][n][k-paired] fp16 hi/lo
__device__ __align__(16) __half g_W1h[NE * HID * DIN];
__device__ __align__(16) __half g_W1l[NE * HID * DIN];
__device__ __align__(16) __half g_W2h[NE * HID * HID];
__device__ __align__(16) __half g_W2l[NE * HID * HID];
__device__ __align__(16) __half g_W3h[NE * DOUT * HID];
__device__ __align__(16) __half g_W3l[NE * DOUT * HID];
// X: [(b*NE+e)][k-paired 128] fp16 hi/lo
__device__ __align__(16) __half g_Xh[(size_t)BATCH * NE * DIN];
__device__ __align__(16) __half g_Xl[(size_t)BATCH * NE * DIN];
__device__ float g_part[(size_t)NE * BATCH * DOUT];

// k-pairing permutation within each 16-k block: fragment halves
// (2t,2t+1,2t+8,2t+9) become contiguous at position t*4..t*4+3.
__host__ __device__ __forceinline__ int kperm(int k) {
    int b = k & ~15, kb = k & 15;
    int t, u;
    if (kb < 8) { t = kb >> 1; u = kb & 1; }
    else        { t = (kb - 8) >> 1; u = 2 + (kb & 1); }
    return b + t * 4 + u;
}

// ---------------- smem map (bytes) ----------------
#define SM_H1H  0         // h1 hi: 64 rows x 520 halves (1040B stride)
#define SM_H1L  66560
#define SM_H2H  133120    // h2 hi: 64 rows x 72 halves (144B stride)
#define SM_H2L  142336
#define SM_B1   151552
#define SM_B2   153600
#define SM_B3   155648
#define SMEM_SZ 155904

__device__ __forceinline__ void mma16816(float* c, uint32_t a0, uint32_t a1, uint32_t a2,
                                         uint32_t a3, uint32_t b0, uint32_t b1) {
    asm volatile(
        "mma.sync.aligned.m16n8k16.row.col.f32.f16.f16.f32 "
        "{%0,%1,%2,%3},{%4,%5,%6,%7},{%8,%9},{%0,%1,%2,%3};"
        : "+f"(c[0]), "+f"(c[1]), "+f"(c[2]), "+f"(c[3])
        : "r"(a0), "r"(a1), "r"(a2), "r"(a3), "r"(b0), "r"(b1));
}

// K=64 panel, warp tile 16m x 32n, A + B both from GLOBAL (k-paired), 3-term.
// aH0/aL0: &A[row mrow][t*4]; arow8: +8 rows (halves). bH/bL: &B[nrow0+g][t*4].
__device__ __forceinline__ void gemm_ag(float* acc,
                                        const __half* aH0, const __half* aL0, size_t arow8,
                                        const __half* bH, const __half* bL, size_t bstr) {
#pragma unroll
    for (int k16 = 0; k16 < 4; k16++) {
        const int ko = k16 * 16;
        uint2 ah0 = *(const uint2*)(aH0 + ko);
        uint2 ah1 = *(const uint2*)(aH0 + arow8 + ko);
        uint2 al0 = *(const uint2*)(aL0 + ko);
        uint2 al1 = *(const uint2*)(aL0 + arow8 + ko);
#pragma unroll
        for (int nb = 0; nb < 4; nb++) {
            uint2 bh = *(const uint2*)(bH + (size_t)nb * 8 * bstr + ko);
            uint2 bl = *(const uint2*)(bL + (size_t)nb * 8 * bstr + ko);
            float* c = acc + nb * 4;
            mma16816(c, ah0.x, ah1.x, ah0.y, ah1.y, bh.x, bh.y);
            mma16816(c, al0.x, al1.x, al0.y, al1.y, bh.x, bh.y);
            mma16816(c, ah0.x, ah1.x, ah0.y, ah1.y, bl.x, bl.y);
        }
    }
}

// K=64 panel, A from SMEM (plain layout, lds.b32 frags), B from GLOBAL (k-paired).
__device__ __forceinline__ void gemm_as(float* acc, const char* sm,
                                        uint32_t aHb, uint32_t aLoff, uint32_t astrB,
                                        const __half* bH, const __half* bL, size_t bstr) {
#pragma unroll
    for (int k16 = 0; k16 < 4; k16++) {
        uint32_t o = aHb + k16 * 32;
        uint32_t a0 = *(const uint32_t*)(sm + o);
        uint32_t a1 = *(const uint32_t*)(sm + o + astrB * 8);
        uint32_t a2 = *(const uint32_t*)(sm + o + 16);
        uint32_t a3 = *(const uint32_t*)(sm + o + astrB * 8 + 16);
        uint32_t l0 = *(const uint32_t*)(sm + o + aLoff);
        uint32_t l1 = *(const uint32_t*)(sm + o + aLoff + astrB * 8);
        uint32_t l2 = *(const uint32_t*)(sm + o + aLoff + 16);
        uint32_t l3 = *(const uint32_t*)(sm + o + aLoff + astrB * 8 + 16);
        const int ko = k16 * 16;
#pragma unroll
        for (int nb = 0; nb < 4; nb++) {
            uint2 bh = *(const uint2*)(bH + (size_t)nb * 8 * bstr + ko);
            uint2 bl = *(const uint2*)(bL + (size_t)nb * 8 * bstr + ko);
            float* c = acc + nb * 4;
            mma16816(c, a0, a1, a2, a3, bh.x, bh.y);
            mma16816(c, l0, l1, l2, l3, bh.x, bh.y);
            mma16816(c, a0, a1, a2, a3, bl.x, bl.y);
        }
    }
}

__device__ __forceinline__ void split_st(char* sm, uint32_t oh, int lod, float v0, float v1) {
    __half h0 = __float2half_rn(v0), h1 = __float2half_rn(v1);
    __half l0 = __float2half_rn(v0 - __half2float(h0));
    __half l1 = __float2half_rn(v1 - __half2float(h1));
    *(__half2*)(sm + oh) = __halves2half2(h0, h1);
    *(__half2*)(sm + oh + lod) = __halves2half2(l0, l1);
}

// relu(acc+bias) -> hi/lo fp16, warp tile 16x32 (rows r0, r0+8)
__device__ __forceinline__ void epi_relu(char* sm, uint32_t dstH, int lod, int strB,
                                         const float* bias, const float* acc,
                                         int r0, int cw) {
#pragma unroll
    for (int nb = 0; nb < 4; nb++) {
        const float* c = acc + nb * 4;
        int cc = cw + nb * 8;
        float v00 = fmaxf(c[0] + bias[cc], 0.f);
        float v01 = fmaxf(c[1] + bias[cc + 1], 0.f);
        float v10 = fmaxf(c[2] + bias[cc], 0.f);
        float v11 = fmaxf(c[3] + bias[cc + 1], 0.f);
        split_st(sm, dstH + r0 * strB + cc * 2, lod, v00, v01);
        split_st(sm, dstH + (r0 + 8) * strB + cc * 2, lod, v10, v11);
    }
}

// ---------------- prologue: weight transpose + split + k-pairing ----------------
__global__ void tsplit(const float* __restrict__ src, int which, int K, int N) {
    __shared__ float t[32][33];
    __half *dh, *dl;
    if (which == 0) { dh = g_W1h; dl = g_W1l; }
    else if (which == 1) { dh = g_W2h; dl = g_W2l; }
    else { dh = g_W3h; dl = g_W3l; }
    int e = blockIdx.z, k0 = blockIdx.x * 32, n0 = blockIdx.y * 32;
    int tx = threadIdx.x, ty = threadIdx.y;
    const float* s = src + (size_t)e * K * N;
#pragma unroll
    for (int i = 0; i < 32; i += 8)
        t[ty + i][tx] = s[(size_t)(k0 + ty + i) * N + n0 + tx];
    __syncthreads();
#pragma unroll
    for (int i = 0; i < 32; i += 8) {
        float v = t[tx][ty + i];
        __half h = __float2half_rn(v);
        size_t o = (size_t)e * N * K + (size_t)(n0 + ty + i) * K + kperm(k0 + tx);
        dh[o] = h;
        dl[o] = __float2half_rn(v - __half2float(h));
    }
}

// ---------------- prologue: X split + k-pairing ----------------
__global__ void xsplit(const float* __restrict__ x) {
    size_t i = (size_t)blockIdx.x * blockDim.x + threadIdx.x;  // over B*E*DIN
    float v = x[i];
    int k = (int)(i & (DIN - 1));
    size_t row = i >> 7;
    __half h = __float2half_rn(v);
    size_t o = row * DIN + kperm(k);
    g_Xh[o] = h;
    g_Xl[o] = __float2half_rn(v - __half2float(h));
}

// ---------------- main fused kernel: 256 thr, 8 warps 16x32, barrier-light ----------------
__global__ void __launch_bounds__(256, 1)
moe_main(const float* __restrict__ b1, const float* __restrict__ b2,
         const float* __restrict__ b3) {
    extern __shared__ char sm[];
    const int tid = threadIdx.x, wid = tid >> 5, lid = tid & 31;
    const int g = lid >> 2, t = lid & 3;
    const int wR = wid & 3, wC = wid >> 2;           // 4 m-slices x 2 n-cols
    const int m0 = blockIdx.x * 64, e = blockIdx.y;
    const int mrow = wR * 16 + g, cw = wC * 32 + t * 2;

    float* b1s = (float*)(sm + SM_B1);
    float* b2s = (float*)(sm + SM_B2);
    float* b3s = (float*)(sm + SM_B3);
    for (int i = tid; i < HID; i += 256) {
        b1s[i] = b1[e * HID + i];
        b2s[i] = b2[e * HID + i];
    }
    if (tid < DOUT) b3s[tid] = b3[e * DOUT + tid];
    __syncthreads();   // biases visible before first epilogue

    // A pointers for phase 1 (X rows, k-paired global)
    const size_t xrow = ((size_t)(m0 + mrow) * NE + e) * DIN;
    const size_t arow8 = (size_t)8 * NE * DIN;
    const __half* aXh = g_Xh + xrow + t * 4;
    const __half* aXl = g_Xl + xrow + t * 4;

    float acc[16];
#pragma unroll
    for (int i = 0; i < 16; i++) acc[i] = 0.f;

    // ---- phase 1: h1 = relu(X @ W1 + b1); NO barriers (warp-private h1 tiles) ----
    for (int P = 0; P < 16; ++P) {
        int nc = P >> 1, kh = P & 1;
        const size_t wrow = ((size_t)e * HID + nc * 64 + wC * 32 + g) * DIN + kh * 64 + t * 4;
        gemm_ag(acc, aXh + kh * 64, aXl + kh * 64, arow8,
                g_W1h + wrow, g_W1l + wrow, DIN);
        if (kh) {
            epi_relu(sm, SM_H1H + nc * 128, SM_H1L - SM_H1H, 1040,
                     b1s + nc * 64, acc, mrow, cw);
#pragma unroll
            for (int i = 0; i < 16; i++) acc[i] = 0.f;
        }
    }
    __syncthreads();   // h1 complete

    // ---- phase 2: per 64-col chunk: 8 W2 panels (no barriers) + h2 + W3 ----
    float out[16];
#pragma unroll
    for (int i = 0; i < 16; i++) out[i] = 0.f;

    const uint32_t aH1 = SM_H1H + (uint32_t)(mrow * 1040 + t * 4);
    const uint32_t aH2 = SM_H2H + (uint32_t)(mrow * 144 + t * 4);

    for (int nc = 0; nc < 8; ++nc) {
#pragma unroll
        for (int i = 0; i < 16; i++) acc[i] = 0.f;
        const size_t w2row = ((size_t)e * HID + nc * 64 + wC * 32 + g) * HID + t * 4;
#pragma unroll 1
        for (int j = 0; j < 8; ++j) {
            gemm_as(acc, sm, aH1 + j * 128, SM_H1L - SM_H1H, 1040,
                    g_W2h + w2row + j * 64, g_W2l + w2row + j * 64, HID);
        }
        epi_relu(sm, SM_H2H, SM_H2L - SM_H2H, 144, b2s + nc * 64, acc, mrow, cw);
        __syncthreads();   // h2 chunk complete
        const size_t w3row = ((size_t)e * DOUT + wC * 32 + g) * HID + nc * 64 + t * 4;
        gemm_as(out, sm, aH2, SM_H2L - SM_H2H, 144,
                g_W3h + w3row, g_W3l + w3row, HID);
        __syncthreads();   // h2 reads done before next chunk overwrites
    }

    // ---- write partial [e][m][64] ----
    float* dst = g_part + ((size_t)e * BATCH + m0) * DOUT;
#pragma unroll
    for (int nb = 0; nb < 4; nb++) {
        const float* c = out + nb * 4;
        int cc = cw + nb * 8;
        *(float2*)(dst + (size_t)mrow * DOUT + cc) =
            make_float2(c[0] + b3s[cc], c[1] + b3s[cc + 1]);
        *(float2*)(dst + (size_t)(mrow + 8) * DOUT + cc) =
            make_float2(c[2] + b3s[cc], c[3] + b3s[cc + 1]);
    }
}

// ---------------- deterministic expert reduction ----------------
__global__ void reduce_out(float* __restrict__ out) {
    int i = blockIdx.x * blockDim.x + threadIdx.x;
    float s = 0.f;
#pragma unroll
    for (int e = 0; e < NE; e++) s += g_part[(size_t)e * BATCH * DOUT + i];
    out[i] = s;
}

// ---------------- launcher ----------------
extern "C" void kernel_launch(void* const* d_in, const int* in_sizes, int n_in,
                              void* d_out, int out_size) {
    const float* x  = (const float*)d_in[0];
    const float* W1 = (const float*)d_in[1];
    const float* b1 = (const float*)d_in[2];
    const float* W2 = (const float*)d_in[3];
    const float* b2 = (const float*)d_in[4];
    const float* W3 = (const float*)d_in[5];
    const float* b3 = (const float*)d_in[6];
    float* out = (float*)d_out;

    cudaFuncSetAttribute(moe_main, cudaFuncAttributeMaxDynamicSharedMemorySize, SMEM_SZ);

    dim3 t32(32, 8);
    tsplit<<<dim3(DIN / 32, HID / 32, NE), t32>>>(W1, 0, DIN, HID);
    tsplit<<<dim3(HID / 32, HID / 32, NE), t32>>>(W2, 1, HID, HID);
    tsplit<<<dim3(HID / 32, DOUT / 32, NE), t32>>>(W3, 2, HID, DOUT);
    xsplit<<<(int)(((size_t)BATCH * NE * DIN) / 256), 256>>>(x);

    moe_main<<<dim3(BATCH / 64, NE), 256, SMEM_SZ>>>(b1, b2, b3);

    reduce_out<<<(BATCH * DOUT) / 256, 256>>>(out);
}

// round 11
// speedup vs baseline: 1.7441x; 1.7441x over previous
#include <cuda_runtime.h>
#include <cuda_fp16.h>
#include <cstdint>

#define NE 16
#define DIN 128
#define HID 512
#define DOUT 64
#define BATCH 8192

// ---------------- device scratch (16B aligned for cp.async) ----------------
__device__ __align__(16) __half g_W1h[NE * HID * DIN];
__device__ __align__(16) __half g_W1l[NE * HID * DIN];
__device__ __align__(16) __half g_W2h[NE * HID * HID];
__device__ __align__(16) __half g_W2l[NE * HID * HID];
__device__ __align__(16) __half g_W3h[NE * DOUT * HID];
__device__ __align__(16) __half g_W3l[NE * DOUT * HID];
__device__ float g_part[(size_t)NE * BATCH * DOUT];

// ---------------- smem map (bytes) ----------------
// X / h2 region: 64 rows x 136 halves (272B stride) hi + lo
#define SM_XH   0
#define SM_XL   17408
// per-group weight buffers: 2 groups x 3 bufs x 9216 (hi 4608 + lo 4608)
#define SM_BUF  34816
#define GBUF_SZ 27648
#define BUF_SZ  9216
// h1: 64 rows x 520 halves (1040B stride) hi + lo
#define SM_H1H  90112
#define SM_H1L  156672
#define SMEM_SZ 223232

__device__ __forceinline__ uint32_t smem_u32(const void* p) {
    uint32_t a;
    asm("{ .reg .u64 t; cvta.to.shared.u64 t, %1; cvt.u32.u64 %0, t; }" : "=r"(a) : "l"(p));
    return a;
}
#define CP_COMMIT asm volatile("cp.async.commit_group;" ::: "memory")
#define CP_WAIT1  asm volatile("cp.async.wait_group 1;" ::: "memory")
#define GROUP_BAR(id) asm volatile("bar.sync %0, 128;" :: "r"(id) : "memory")

__device__ __forceinline__ void mma16816(float* c, uint32_t a0, uint32_t a1, uint32_t a2,
                                         uint32_t a3, uint32_t b0, uint32_t b1) {
    asm volatile(
        "mma.sync.aligned.m16n8k16.row.col.f32.f16.f16.f32 "
        "{%0,%1,%2,%3},{%4,%5,%6,%7},{%8,%9},{%0,%1,%2,%3};"
        : "+f"(c[0]), "+f"(c[1]), "+f"(c[2]), "+f"(c[3])
        : "r"(a0), "r"(a1), "r"(a2), "r"(a3), "r"(b0), "r"(b1));
}

// ---------------- panel source schedule (64n x 64k panels) ----------------
struct Src { const __half* h; const __half* l; int stride; };

__device__ __forceinline__ Src panel_src(int e, int P) {
    Src s;
    if (P < 16) {
        int nc = P >> 1, hf = P & 1;
        size_t o = ((size_t)e * HID + nc * 64) * DIN + hf * 64;
        s.h = g_W1h + o; s.l = g_W1l + o; s.stride = DIN;
        return s;
    }
    int Q = P - 16, nc = Q / 9, j = Q - nc * 9;
    if (j < 8) {
        size_t o = ((size_t)e * HID + nc * 64) * HID + j * 64;
        s.h = g_W2h + o; s.l = g_W2l + o; s.stride = HID;
        return s;
    }
    size_t o = (size_t)e * DOUT * HID + nc * 64;
    s.h = g_W3h + o; s.l = g_W3l + o; s.stride = HID;
    return s;
}

// group slice load: 32 n-rows (this group's half) hi+lo into group buffer.
// 128 threads (gt = tid&127), 4 cp.async each. Row stride 144B, lo at +4608.
__device__ __forceinline__ void load_slice(uint32_t sb, uint32_t buf, Src s,
                                           int wC, int gt) {
#pragma unroll
    for (int i = 0; i < 2; i++) {
        int idx = gt + i * 128;                  // 0..255
        int r = idx >> 3, j = idx & 7;           // r: 0..31, j: 0..7 (16B chunks)
        uint32_t d = sb + buf + r * 144 + j * 16;
        const __half* pH = s.h + (size_t)(wC * 32 + r) * s.stride + j * 8;
        const __half* pL = s.l + (size_t)(wC * 32 + r) * s.stride + j * 8;
        asm volatile("cp.async.cg.shared.global [%0], [%1], 16;" :: "r"(d), "l"(pH));
        asm volatile("cp.async.cg.shared.global [%0], [%1], 16;" :: "r"(d + 4608), "l"(pL));
    }
}

// K=64 panel, warp tile 16m x 32n, 3-term: Ah*Wh + Al*Wh + Ah*Wl
// B rows 0..31 of group buffer (row stride 144B, lo at +4608)
__device__ __forceinline__ void gemm_panel(const char* sm, uint32_t aH, uint32_t aLd,
                                           uint32_t astr, uint32_t wb, float* acc) {
#pragma unroll
    for (int k16 = 0; k16 < 4; k16++) {
        uint32_t o = aH + k16 * 32;
        uint32_t a0 = *(const uint32_t*)(sm + o);
        uint32_t a1 = *(const uint32_t*)(sm + o + astr * 8);
        uint32_t a2 = *(const uint32_t*)(sm + o + 16);
        uint32_t a3 = *(const uint32_t*)(sm + o + astr * 8 + 16);
        uint32_t l0 = *(const uint32_t*)(sm + o + aLd);
        uint32_t l1 = *(const uint32_t*)(sm + o + aLd + astr * 8);
        uint32_t l2 = *(const uint32_t*)(sm + o + aLd + 16);
        uint32_t l3 = *(const uint32_t*)(sm + o + aLd + astr * 8 + 16);
#pragma unroll
        for (int nb = 0; nb < 4; nb++) {
            uint32_t bo = wb + nb * (8 * 144) + k16 * 32;
            uint32_t b0 = *(const uint32_t*)(sm + bo);
            uint32_t b1 = *(const uint32_t*)(sm + bo + 16);
            uint32_t w0 = *(const uint32_t*)(sm + bo + 4608);
            uint32_t w1 = *(const uint32_t*)(sm + bo + 4608 + 16);
            float* c = acc + nb * 4;
            mma16816(c, a0, a1, a2, a3, b0, b1);
            mma16816(c, l0, l1, l2, l3, b0, b1);
            mma16816(c, a0, a1, a2, a3, w0, w1);
        }
    }
}

__device__ __forceinline__ void split_st(char* sm, uint32_t oh, int lod, float v0, float v1) {
    __half h0 = __float2half_rn(v0), h1 = __float2half_rn(v1);
    __half l0 = __float2half_rn(v0 - __half2float(h0));
    __half l1 = __float2half_rn(v1 - __half2float(h1));
    *(__half2*)(sm + oh) = __halves2half2(h0, h1);
    *(__half2*)(sm + oh + lod) = __halves2half2(l0, l1);
}

// relu(acc+bias_global) -> hi/lo fp16, warp tile 16x32 (rows r0, r0+8)
__device__ __forceinline__ void epi_relu(char* sm, uint32_t dstH, int lod, int strB,
                                         const float* __restrict__ bias, const float* acc,
                                         int r0, int cw) {
#pragma unroll
    for (int nb = 0; nb < 4; nb++) {
        const float* c = acc + nb * 4;
        int cc = cw + nb * 8;
        float bz0 = __ldg(bias + cc), bz1 = __ldg(bias + cc + 1);
        float v00 = fmaxf(c[0] + bz0, 0.f);
        float v01 = fmaxf(c[1] + bz1, 0.f);
        float v10 = fmaxf(c[2] + bz0, 0.f);
        float v11 = fmaxf(c[3] + bz1, 0.f);
        split_st(sm, dstH + r0 * strB + cc * 2, lod, v00, v01);
        split_st(sm, dstH + (r0 + 8) * strB + cc * 2, lod, v10, v11);
    }
}

// ---------------- prologue: transpose + fp16 hi/lo split ----------------
__global__ void tsplit(const float* __restrict__ src, int which, int K, int N) {
    __shared__ float t[32][33];
    __half *dh, *dl;
    if (which == 0) { dh = g_W1h; dl = g_W1l; }
    else if (which == 1) { dh = g_W2h; dl = g_W2l; }
    else { dh = g_W3h; dl = g_W3l; }
    int e = blockIdx.z, k0 = blockIdx.x * 32, n0 = blockIdx.y * 32;
    int tx = threadIdx.x, ty = threadIdx.y;
    const float* s = src + (size_t)e * K * N;
#pragma unroll
    for (int i = 0; i < 32; i += 8)
        t[ty + i][tx] = s[(size_t)(k0 + ty + i) * N + n0 + tx];
    __syncthreads();
#pragma unroll
    for (int i = 0; i < 32; i += 8) {
        float v = t[tx][ty + i];
        __half h = __float2half_rn(v);
        size_t o = (size_t)e * N * K + (size_t)(n0 + ty + i) * K + k0 + tx;
        dh[o] = h;
        dl[o] = __float2half_rn(v - __half2float(h));
    }
}

// ---------------- main fused kernel: 256 thr, two 4-warp pipeline groups ----------------
__global__ void __launch_bounds__(256, 1)
moe_main(const float* __restrict__ x, const float* __restrict__ b1,
         const float* __restrict__ b2, const float* __restrict__ b3) {
    extern __shared__ char sm[];
    const int tid = threadIdx.x, wid = tid >> 5, lid = tid & 31;
    const int g = lid >> 2, t = lid & 3;
    const int wR = wid & 3, wC = wid >> 2;     // group = wC (warps 0-3 / 4-7)
    const int gt = tid & 127;                  // thread id within group
    const int m0 = blockIdx.x * 64, e = blockIdx.y;
    const uint32_t sb = smem_u32(sm);
    const uint32_t gbuf = SM_BUF + (uint32_t)wC * GBUF_SZ;

    // prefetch group slices for panels 0,1 (overlap with X conversion)
    load_slice(sb, gbuf + 0 * BUF_SZ, panel_src(e, 0), wC, gt); CP_COMMIT;
    load_slice(sb, gbuf + 1 * BUF_SZ, panel_src(e, 1), wC, gt); CP_COMMIT;

    // X tile [64 x 128] -> fp16 hi/lo, row stride 136 halves (272 B)
    for (int i = tid; i < 2048; i += 256) {
        int r = i >> 5, j = i & 31;
        float4 f = ((const float4*)(x + ((size_t)(m0 + r) * NE + e) * DIN))[j];
        uint32_t o = (uint32_t)(r * 136 + j * 4) * 2;
        split_st(sm, SM_XH + o, SM_XL - SM_XH, f.x, f.y);
        split_st(sm, SM_XH + o + 4, SM_XL - SM_XH, f.z, f.w);
    }
    __syncthreads();   // X visible to all warps

    // per-lane fragment bases
    const int mrow = wR * 16 + g, cw = wC * 32 + t * 2;
    const uint32_t aXb  = SM_XH  + (uint32_t)(mrow * 272 + t * 4);
    const uint32_t aH1b = SM_H1H + (uint32_t)(mrow * 1040 + t * 4);
    const uint32_t aH2b = SM_XH  + (uint32_t)(mrow * 144 + t * 4);
    const uint32_t wbLane = (uint32_t)(g * 144 + t * 4);
    const float* b1e = b1 + e * HID;
    const float* b2e = b2 + e * HID;
    const float* b3e = b3 + e * DOUT;

    float acc[16], out[16];
#pragma unroll
    for (int i = 0; i < 16; i++) { acc[i] = 0.f; out[i] = 0.f; }

    // ---- flat 88-panel pipeline, group-private buffers, group barriers ----
    for (int P = 0; P < 88; ++P) {
        CP_WAIT1;                  // own slice for panel P complete
        GROUP_BAR(1 + wC);         // whole group's slice complete; gemm P-1 done
        if (P + 2 < 88)
            load_slice(sb, gbuf + ((P + 2) % 3) * BUF_SZ, panel_src(e, P + 2), wC, gt);
        CP_COMMIT;
        const uint32_t wb = gbuf + (P % 3) * BUF_SZ + wbLane;

        if (P < 16) {
            gemm_panel(sm, aXb + (P & 1) * 128, SM_XL - SM_XH, 272, wb, acc);
            if (P & 1) {
                int nc = P >> 1;
                epi_relu(sm, SM_H1H + nc * 128, SM_H1L - SM_H1H, 1040,
                         b1e + nc * 64, acc, mrow, cw);
#pragma unroll
                for (int i = 0; i < 16; i++) acc[i] = 0.f;
            }
            if (P == 15) __syncthreads();   // h1 complete for all warps
        } else {
            int Q = P - 16, nc = Q / 9, j = Q - nc * 9;
            if (j < 8) {
                gemm_panel(sm, aH1b + j * 128, SM_H1L - SM_H1H, 1040, wb, acc);
                if (j == 7) {
                    // h2 chunk -> X region (row stride 144 B)
                    epi_relu(sm, SM_XH, SM_XL - SM_XH, 144, b2e + nc * 64, acc, mrow, cw);
#pragma unroll
                    for (int i = 0; i < 16; i++) acc[i] = 0.f;
                    __syncthreads();        // h2 visible before W3 panel reads it
                }
            } else {
                gemm_panel(sm, aH2b, SM_XL - SM_XH, 144, wb, out);
                __syncthreads();            // h2 reads done before next chunk epi
            }
        }
    }

    // ---- write partial [e][m][64] ----
    float* dst = g_part + ((size_t)e * BATCH + m0) * DOUT;
#pragma unroll
    for (int nb = 0; nb < 4; nb++) {
        const float* c = out + nb * 4;
        int cc = cw + nb * 8;
        float bz0 = __ldg(b3e + cc), bz1 = __ldg(b3e + cc + 1);
        *(float2*)(dst + (size_t)mrow * DOUT + cc) = make_float2(c[0] + bz0, c[1] + bz1);
        *(float2*)(dst + (size_t)(mrow + 8) * DOUT + cc) = make_float2(c[2] + bz0, c[3] + bz1);
    }
}

// ---------------- deterministic expert reduction ----------------
__global__ void reduce_out(float* __restrict__ out) {
    int i = blockIdx.x * blockDim.x + threadIdx.x;
    float s = 0.f;
#pragma unroll
    for (int e = 0; e < NE; e++) s += g_part[(size_t)e * BATCH * DOUT + i];
    out[i] = s;
}

// ---------------- launcher ----------------
extern "C" void kernel_launch(void* const* d_in, const int* in_sizes, int n_in,
                              void* d_out, int out_size) {
    const float* x  = (const float*)d_in[0];
    const float* W1 = (const float*)d_in[1];
    const float* b1 = (const float*)d_in[2];
    const float* W2 = (const float*)d_in[3];
    const float* b2 = (const float*)d_in[4];
    const float* W3 = (const float*)d_in[5];
    const float* b3 = (const float*)d_in[6];
    float* out = (float*)d_out;

    cudaFuncSetAttribute(moe_main, cudaFuncAttributeMaxDynamicSharedMemorySize, SMEM_SZ);

    dim3 t32(32, 8);
    tsplit<<<dim3(DIN / 32, HID / 32, NE), t32>>>(W1, 0, DIN, HID);
    tsplit<<<dim3(HID / 32, HID / 32, NE), t32>>>(W2, 1, HID, HID);
    tsplit<<<dim3(HID / 32, DOUT / 32, NE), t32>>>(W3, 2, HID, DOUT);

    moe_main<<<dim3(BATCH / 64, NE), 256, SMEM_SZ>>>(x, b1, b2, b3);

    reduce_out<<<(BATCH * DOUT) / 256, 256>>>(out);
}